// round 1
// baseline (speedup 1.0000x reference)
#include <cuda_runtime.h>
#include <cuda_bf16.h>

// CostVolume: cost[b,i,h,x] = mean_c L[b,c,h,x] * R[b,c,h,x-i], zero for x<i.
// Shapes: b=8, c=128, h=96, w=320, 48 disparities. fp32 in/out.

#define BB 8
#define CH 128
#define HH 96
#define WW 320
#define MAXD 48

#define TX 64      // x-tile per block
#define CC 16      // channel chunk
#define RW 112     // R smem window floats: [x0-48, x0+64)
#define NTHR 96    // 16 (tx) x 6 (ty)

__global__ __launch_bounds__(NTHR, 8)
void costvol_kernel(const float* __restrict__ L,
                    const float* __restrict__ R,
                    float* __restrict__ out)
{
    __shared__ float Ls[CC][TX];
    __shared__ float Rs[CC][RW];

    const int tid = threadIdx.x;
    const int tx  = tid & 15;   // 0..15 : x quad
    const int ty  = tid >> 4;   // 0..5  : group of 8 disparities

    int blk = blockIdx.x;
    int xt  = blk % 5;          // 5 x-tiles of 64
    int bh  = blk / 5;
    int h   = bh % HH;
    int b   = bh / HH;
    int x0  = xt * TX;

    const size_t plane = (size_t)HH * WW;          // per-channel stride
    const float* Lb = L + ((size_t)b * CH * HH + h) * WW;  // + c*plane
    const float* Rb = R + ((size_t)b * CH * HH + h) * WW;

    float acc[8][4];
    #pragma unroll
    for (int a = 0; a < 8; a++)
        #pragma unroll
        for (int e = 0; e < 4; e++) acc[a][e] = 0.0f;

    const int rbase = 4 * tx - 8 * ty + 40;  // 16B-aligned window start in Rs row

    for (int c0 = 0; c0 < CH; c0 += CC) {
        // ---- load L chunk: CC rows x 16 float4 (coalesced) ----
        #pragma unroll 1
        for (int idx = tid; idx < CC * (TX / 4); idx += NTHR) {
            int row  = idx >> 4;          // / (TX/4)
            int col4 = idx & 15;
            const float4* src = (const float4*)(Lb + (size_t)(c0 + row) * plane + x0) + col4;
            ((float4*)Ls[row])[col4] = *src;
        }
        // ---- load R chunk: CC rows x 28 float4, window [x0-48, x0+64) ----
        #pragma unroll 1
        for (int idx = tid; idx < CC * (RW / 4); idx += NTHR) {
            int row  = idx / (RW / 4);
            int col4 = idx % (RW / 4);
            int j = x0 - 48 + col4 * 4;
            const float* rrow = Rb + (size_t)(c0 + row) * plane;
            float4 v;
            if (j >= 0) {
                v = *(const float4*)(rrow + j);
            } else {
                float t0 = (j + 0 >= 0) ? rrow[j + 0] : 0.0f;
                float t1 = (j + 1 >= 0) ? rrow[j + 1] : 0.0f;
                float t2 = (j + 2 >= 0) ? rrow[j + 2] : 0.0f;
                float t3 = (j + 3 >= 0) ? rrow[j + 3] : 0.0f;
                v = make_float4(t0, t1, t2, t3);
            }
            ((float4*)Rs[row])[col4] = v;
        }
        __syncthreads();

        // ---- compute: 32 FMA per c per thread, 4 LDS.128 per c ----
        #pragma unroll
        for (int cc = 0; cc < CC; cc++) {
            float4 lv = ((const float4*)Ls[cc])[tx];
            float lf[4] = {lv.x, lv.y, lv.z, lv.w};

            float4 r0 = *(const float4*)&Rs[cc][rbase];
            float4 r1 = *(const float4*)&Rs[cc][rbase + 4];
            float4 r2 = *(const float4*)&Rs[cc][rbase + 8];
            float r[12] = {r0.x, r0.y, r0.z, r0.w,
                           r1.x, r1.y, r1.z, r1.w,
                           r2.x, r2.y, r2.z, r2.w};

            // out(i=8ty+a, x=x0+4tx+e) += L[e] * R[x-i] = lf[e] * r[e - a + 8]
            #pragma unroll
            for (int a = 0; a < 8; a++)
                #pragma unroll
                for (int e = 0; e < 4; e++)
                    acc[a][e] += lf[e] * r[e - a + 8];
        }
        __syncthreads();
    }

    // ---- write: 8 x STG.128, coalesced across tx ----
    const float scale = 1.0f / 128.0f;
    const int i0 = 8 * ty;
    #pragma unroll
    for (int a = 0; a < 8; a++) {
        float4 v = make_float4(acc[a][0] * scale, acc[a][1] * scale,
                               acc[a][2] * scale, acc[a][3] * scale);
        float* dst = out + (((size_t)b * MAXD + (i0 + a)) * HH + h) * WW + x0 + 4 * tx;
        *(float4*)dst = v;
    }
}

extern "C" void kernel_launch(void* const* d_in, const int* in_sizes, int n_in,
                              void* d_out, int out_size)
{
    const float* L = (const float*)d_in[0];
    const float* R = (const float*)d_in[1];
    float* out = (float*)d_out;

    dim3 grid(BB * HH * (WW / TX));  // 8*96*5 = 3840
    dim3 block(NTHR);
    costvol_kernel<<<grid, block>>>(L, R, out);
}